// round 11
// baseline (speedup 1.0000x reference)
#include <cuda_runtime.h>
#include <cuda_bf16.h>
#include <math.h>
#include <stdint.h>

#define T_TOK 512
#define D_DIM 1024
#define E_EXP 64
#define F_INT 512
#define TOPK  4

#define ROWB 144   // 64 bf16 = 128B data + 16B pad: conflict-free ldmatrix, swizzle-free
#define NTOK 64    // tokens per tile pass (covers ~all experts in one pass)

// ---------------- persistent device scratch ----------------------------------
__device__ float g_logits[T_TOK * E_EXP];
__device__ float g_topk_w[T_TOK * TOPK];
__device__ int   g_exp_cnt[E_EXP];
__device__ int   g_exp_tok[E_EXP * T_TOK];                 // entry = token*4 + slot
__device__ __nv_bfloat16 g_Hhi[T_TOK * TOPK * F_INT];      // 2 MB
__device__ __nv_bfloat16 g_Hlo[T_TOK * TOPK * F_INT];      // 2 MB
__device__ float g_Y[T_TOK * TOPK * D_DIM];                // 8 MB

// ---------------- helpers -----------------------------------------------------
__device__ __forceinline__ uint32_t smem_u32(const void* p) {
    uint32_t a;
    asm("{ .reg .u64 t; cvta.to.shared.u64 t, %1; cvt.u32.u64 %0, t; }" : "=r"(a) : "l"(p));
    return a;
}
__device__ __forceinline__ void ldm4(uint32_t* r, uint32_t a) {
    asm volatile("ldmatrix.sync.aligned.m8n8.x4.shared.b16 {%0,%1,%2,%3}, [%4];"
        : "=r"(r[0]), "=r"(r[1]), "=r"(r[2]), "=r"(r[3]) : "r"(a));
}
__device__ __forceinline__ void mma16816(float* d, const uint32_t* a, const uint32_t* b) {
    asm volatile("mma.sync.aligned.m16n8k16.row.col.f32.bf16.bf16.f32 "
        "{%0,%1,%2,%3}, {%4,%5,%6,%7}, {%8,%9}, {%0,%1,%2,%3};"
        : "+f"(d[0]), "+f"(d[1]), "+f"(d[2]), "+f"(d[3])
        : "r"(a[0]), "r"(a[1]), "r"(a[2]), "r"(a[3]), "r"(b[0]), "r"(b[1]));
}
__device__ __forceinline__ uint32_t pack_bf2(__nv_bfloat16 a, __nv_bfloat16 b) {
    return (uint32_t)__bfloat16_as_ushort(a) | ((uint32_t)__bfloat16_as_ushort(b) << 16);
}
// split 8 contiguous fp32 into 16B bf16-hi + 16B bf16-lo
__device__ __forceinline__ void cvt_split8(const float4* v, uint4& h, uint4& l) {
    const float* f = (const float*)v;
    uint32_t hp[4], lp[4];
#pragma unroll
    for (int i = 0; i < 4; i++) {
        float a = f[2 * i], b = f[2 * i + 1];
        __nv_bfloat16 ha = __float2bfloat16(a), hb = __float2bfloat16(b);
        hp[i] = pack_bf2(ha, hb);
        lp[i] = pack_bf2(__float2bfloat16(a - __bfloat162float(ha)),
                         __float2bfloat16(b - __bfloat162float(hb)));
    }
    h = make_uint4(hp[0], hp[1], hp[2], hp[3]);
    l = make_uint4(lp[0], lp[1], lp[2], lp[3]);
}
__device__ __forceinline__ void sts8(const float4* v, char* hi, char* lo, int off) {
    uint4 h, l;
    cvt_split8(v, h, l);
    *(uint4*)(hi + off) = h;
    *(uint4*)(lo + off) = l;
}
// thread owns 8 contiguous floats of a [64 x 64] fp32 chunk: r = tid>>3, q = tid&7
__device__ __forceinline__ void ldg8(float4* v, const float* rowbase, int k0, int q) {
    v[0] = *(const float4*)(rowbase + k0 + (q << 3));
    v[1] = *(const float4*)(rowbase + k0 + (q << 3) + 4);
}

// ---------------- 1: router logits (block 0 also zeroes expert counts) --------
__global__ __launch_bounds__(256) void logits_kernel(
    const float* __restrict__ x, const float* __restrict__ gw)
{
    const int tblk = blockIdx.x * 16;
    const int tid  = threadIdx.x;
    if (blockIdx.x == 0 && tid < E_EXP) g_exp_cnt[tid] = 0;
    __shared__ __align__(16) float As[32][20];
    __shared__ __align__(16) float Bs[32][68];
    const int ttok = (tid >> 5) << 1;
    const int te   = (tid & 31) << 1;
    float acc00 = 0.f, acc01 = 0.f, acc10 = 0.f, acc11 = 0.f;

    for (int k0 = 0; k0 < D_DIM; k0 += 32) {
        if (tid < 128) {
            int tok = tid >> 3, kk4 = tid & 7;
            float4 v = *(const float4*)(x + (size_t)(tblk + tok) * D_DIM + k0 + (kk4 << 2));
            As[(kk4 << 2) + 0][tok] = v.x;
            As[(kk4 << 2) + 1][tok] = v.y;
            As[(kk4 << 2) + 2][tok] = v.z;
            As[(kk4 << 2) + 3][tok] = v.w;
        }
#pragma unroll
        for (int j = 0; j < 2; j++) {
            int idx = tid + (j << 8);
            int r = idx >> 3, kk4 = idx & 7;
            float4 v = *(const float4*)(gw + (size_t)r * D_DIM + k0 + (kk4 << 2));
            Bs[(kk4 << 2) + 0][r] = v.x;
            Bs[(kk4 << 2) + 1][r] = v.y;
            Bs[(kk4 << 2) + 2][r] = v.z;
            Bs[(kk4 << 2) + 3][r] = v.w;
        }
        __syncthreads();
#pragma unroll
        for (int kk = 0; kk < 32; kk++) {
            float a0 = As[kk][ttok], a1 = As[kk][ttok + 1];
            float b0 = Bs[kk][te],   b1 = Bs[kk][te + 1];
            acc00 += a0 * b0; acc01 += a0 * b1;
            acc10 += a1 * b0; acc11 += a1 * b1;
        }
        __syncthreads();
    }
    g_logits[(size_t)(tblk + ttok)     * E_EXP + te]     = acc00;
    g_logits[(size_t)(tblk + ttok)     * E_EXP + te + 1] = acc01;
    g_logits[(size_t)(tblk + ttok + 1) * E_EXP + te]     = acc10;
    g_logits[(size_t)(tblk + ttok + 1) * E_EXP + te + 1] = acc11;
}

// ---------------- 2: per-token top-4 + renorm + expert lists ------------------
__global__ void topk_kernel()
{
    const int t = blockIdx.x;
    const int lane = threadIdx.x;
    float c0 = g_logits[t * E_EXP + lane];
    float c1 = g_logits[t * E_EXP + lane + 32];
    float selv[4]; int seli[4];
#pragma unroll
    for (int s = 0; s < 4; s++) {
        float bv; int bi;
        if (c0 >= c1) { bv = c0; bi = lane; } else { bv = c1; bi = lane + 32; }
#pragma unroll
        for (int off = 16; off > 0; off >>= 1) {
            float ov = __shfl_xor_sync(0xffffffffu, bv, off);
            int   oi = __shfl_xor_sync(0xffffffffu, bi, off);
            if (ov > bv || (ov == bv && oi < bi)) { bv = ov; bi = oi; }
        }
        selv[s] = bv; seli[s] = bi;
        if (bi == lane)      c0 = -3.0e38f;
        if (bi == lane + 32) c1 = -3.0e38f;
    }
    if (lane == 0) {
        float m = selv[0];
        float ew[4]; float sum = 0.f;
#pragma unroll
        for (int s = 0; s < 4; s++) { ew[s] = expf(selv[s] - m); sum += ew[s]; }
        float inv = 1.f / sum;
#pragma unroll
        for (int s = 0; s < 4; s++) {
            g_topk_w[t * 4 + s] = ew[s] * inv;
            int ee = seli[s];
            int pos = atomicAdd(&g_exp_cnt[ee], 1);
            g_exp_tok[ee * T_TOK + pos] = t * 4 + s;
        }
    }
}

// ---------------- 3: Stage A — HMMA gate/up GEMM + in-register SiLU -----------
// CTA = (fchunk 0..7, expert), 512 threads, 2 CTAs/SM.
// Tile: 64 f x 64 tok. Warp grid 4(M) x 4(N); warp tile [16 f x 16 tok].
#define OFF_AGH 0
#define OFF_AGL 9216
#define OFF_AUH 18432
#define OFF_AUL 27648
#define OFF_BH  36864
#define OFF_BL  46080
#define BUF_A   55296

__device__ __forceinline__ void kstepA(uint32_t cb, int s, int a_off, int b_off,
                                       float* accg, float* accu)
{
    const int so = s << 5;
    uint32_t agh[4], agl[4], auh[4], aul[4], bh[4], bl[4];
    ldm4(agh, cb + OFF_AGH + a_off + so);
    ldm4(agl, cb + OFF_AGL + a_off + so);
    ldm4(auh, cb + OFF_AUH + a_off + so);
    ldm4(aul, cb + OFF_AUL + a_off + so);
    ldm4(bh,  cb + OFF_BH  + b_off + so);
    ldm4(bl,  cb + OFF_BL  + b_off + so);
#pragma unroll
    for (int nt = 0; nt < 2; nt++) {
        mma16816(accg + nt * 4, agh, bh + nt * 2);
        mma16816(accg + nt * 4, agl, bh + nt * 2);
        mma16816(accg + nt * 4, agh, bl + nt * 2);
        mma16816(accu + nt * 4, auh, bh + nt * 2);
        mma16816(accu + nt * 4, aul, bh + nt * 2);
        mma16816(accu + nt * 4, auh, bl + nt * 2);
    }
}

__global__ __launch_bounds__(512, 2) void stageA_mma(
    const float* __restrict__ x,
    const float* __restrict__ wg,
    const float* __restrict__ wu)
{
    const int e = blockIdx.y, fc = blockIdx.x;
    const int cnt = g_exp_cnt[e];
    if (cnt == 0) return;
    extern __shared__ __align__(16) char dsm[];
    __shared__ int ent[NTOK];
    const int tid = threadIdx.x, wid = tid >> 5, lane = tid & 31;
    const int wm = wid >> 2, wn = wid & 3;
    const uint32_t smA = smem_u32(dsm);

    const float* wgB = wg + ((size_t)e * F_INT + fc * 64) * D_DIM;
    const float* wuB = wu + ((size_t)e * F_INT + fc * 64) * D_DIM;

    const int a_off = ((wm << 4) + (lane & 15)) * ROWB + ((lane >> 4) << 4);
    const int b_off = ((wn << 4) + ((lane >> 4) << 3) + (lane & 7)) * ROWB
                    + (((lane >> 3) & 1) << 4);
    const int r8 = tid >> 3, q8 = tid & 7;          // loader: row, 8-float segment
    const int soff = r8 * ROWB + (q8 << 4);
    const float* wgRow = wgB + (size_t)r8 * D_DIM;
    const float* wuRow = wuB + (size_t)r8 * D_DIM;

    for (int base = 0; base < cnt; base += NTOK) {
        __syncthreads();
        if (tid < NTOK) ent[tid] = (base + tid < cnt) ? g_exp_tok[e * T_TOK + base + tid] : -1;
        __syncthreads();

        const int en0 = ent[r8];
        const float* xRow = (en0 >= 0) ? (x + (size_t)(en0 >> 2) * D_DIM) : 0;

        {   // prologue: chunk 0 -> buffer 0
            char* B0 = dsm;
            float4 v[2];
            ldg8(v, wgRow, 0, q8); sts8(v, B0 + OFF_AGH, B0 + OFF_AGL, soff);
            ldg8(v, wuRow, 0, q8); sts8(v, B0 + OFF_AUH, B0 + OFF_AUL, soff);
            if (xRow) ldg8(v, xRow, 0, q8);
            else { v[0] = make_float4(0.f, 0.f, 0.f, 0.f); v[1] = v[0]; }
            sts8(v, B0 + OFF_BH, B0 + OFF_BL, soff);
        }
        float accg[8], accu[8];
#pragma unroll
        for (int i = 0; i < 8; i++) { accg[i] = 0.f; accu[i] = 0.f; }

        for (int kt = 0; kt < 16; kt++) {
            __syncthreads();
            const uint32_t cb = smA + (uint32_t)((kt & 1) * BUF_A);
            char* NB = dsm + ((kt + 1) & 1) * BUF_A;
            const bool more = (kt < 15);
            const int k0n = (kt + 1) << 6;

            kstepA(cb, 0, a_off, b_off, accg, accu);
            float4 vg[2], vu[2], vx[2];
            if (more) ldg8(vg, wgRow, k0n, q8);
            kstepA(cb, 1, a_off, b_off, accg, accu);
            if (more) {
                sts8(vg, NB + OFF_AGH, NB + OFF_AGL, soff);
                ldg8(vu, wuRow, k0n, q8);
            }
            kstepA(cb, 2, a_off, b_off, accg, accu);
            if (more) {
                sts8(vu, NB + OFF_AUH, NB + OFF_AUL, soff);
                if (xRow) ldg8(vx, xRow, k0n, q8);
                else { vx[0] = make_float4(0.f, 0.f, 0.f, 0.f); vx[1] = vx[0]; }
            }
            kstepA(cb, 3, a_off, b_off, accg, accu);
            if (more) sts8(vx, NB + OFF_BH, NB + OFF_BL, soff);
        }

        // epilogue: silu(g)*u in regs -> smem transpose -> coalesced bf16 hi/lo
        __syncthreads();
        float* sm_h = (float*)dsm;            // [64 tok][68]
        {
            const int fr = (wm << 4) + (lane >> 2);
            const int tc = (wn << 4) + ((lane & 3) << 1);
#pragma unroll
            for (int nt = 0; nt < 2; nt++) {
#pragma unroll
                for (int q = 0; q < 4; q++) {
                    int f = fr + ((q >> 1) << 3);
                    int t = tc + (nt << 3) + (q & 1);
                    float g = accg[nt * 4 + q], u = accu[nt * 4 + q];
                    float h = g / (1.f + __expf(-g)) * u;
                    sm_h[t * 68 + f] = h;
                }
            }
        }
        __syncthreads();
        {
            const int ec = ent[r8];
            if (ec >= 0) {
                const float4* src = (const float4*)(sm_h + r8 * 68 + (q8 << 3));
                uint4 h, l;
                float4 v[2] = { src[0], src[1] };
                cvt_split8(v, h, l);
                *(uint4*)(g_Hhi + (size_t)ec * F_INT + fc * 64 + (q8 << 3)) = h;
                *(uint4*)(g_Hlo + (size_t)ec * F_INT + fc * 64 + (q8 << 3)) = l;
            }
        }
    }
}

// ---------------- 4: Stage B — HMMA down GEMM --------------------------------
// CTA = (dchunk 0..15, expert), 512 threads, 2 CTAs/SM.
// Tile: 64 d x 64 tok. Warp tile [16 d x 16 tok].
#define OFF_ADH 0
#define OFF_ADL 9216
#define OFF_BBH 18432
#define OFF_BBL 27648
#define BUF_B   36864

__device__ __forceinline__ void kstepB(uint32_t cb, int s, int a_off, int b_off, float* acc)
{
    const int so = s << 5;
    uint32_t adh[4], adl[4], bh[4], bl[4];
    ldm4(adh, cb + OFF_ADH + a_off + so);
    ldm4(adl, cb + OFF_ADL + a_off + so);
    ldm4(bh,  cb + OFF_BBH + b_off + so);
    ldm4(bl,  cb + OFF_BBL + b_off + so);
#pragma unroll
    for (int nt = 0; nt < 2; nt++) {
        mma16816(acc + nt * 4, adh, bh + nt * 2);
        mma16816(acc + nt * 4, adl, bh + nt * 2);
        mma16816(acc + nt * 4, adh, bl + nt * 2);
    }
}

__global__ __launch_bounds__(512, 2) void stageB_mma(const float* __restrict__ wd)
{
    const int e = blockIdx.y, dc = blockIdx.x;
    const int cnt = g_exp_cnt[e];
    if (cnt == 0) return;
    extern __shared__ __align__(16) char dsm[];
    __shared__ int ent[NTOK];
    const int tid = threadIdx.x, wid = tid >> 5, lane = tid & 31;
    const int wm = wid >> 2, wn = wid & 3;
    const uint32_t smA = smem_u32(dsm);

    const float* wdB = wd + ((size_t)e * D_DIM + dc * 64) * F_INT;
    const int a_off = ((wm << 4) + (lane & 15)) * ROWB + ((lane >> 4) << 4);
    const int b_off = ((wn << 4) + ((lane >> 4) << 3) + (lane & 7)) * ROWB
                    + (((lane >> 3) & 1) << 4);
    const int r8 = tid >> 3, q8 = tid & 7;
    const int soff = r8 * ROWB + (q8 << 4);
    const float* wdRow = wdB + (size_t)r8 * F_INT;
    // H gather mapping: 256 threads per (hi|lo) plane, 32B per thread
    const int hidx = tid & 255, hr = hidx >> 2, hq = hidx & 3;
    const int hoff = hr * ROWB + (hq << 5);

    for (int base = 0; base < cnt; base += NTOK) {
        __syncthreads();
        if (tid < NTOK) ent[tid] = (base + tid < cnt) ? g_exp_tok[e * T_TOK + base + tid] : -1;
        __syncthreads();

        const int enH = ent[hr];
        const __nv_bfloat16* hRow = 0;
        if (enH >= 0) hRow = ((tid < 256) ? g_Hhi : g_Hlo) + (size_t)enH * F_INT;
        char* const dstHL = ((tid < 256) ? OFF_BBH : OFF_BBL) + (char*)0;  // offset trick
        const int offHL = (tid < 256) ? OFF_BBH : OFF_BBL;
        (void)dstHL;

        {   // prologue: chunk 0 -> buffer 0
            char* B0 = dsm;
            float4 v[2];
            ldg8(v, wdRow, 0, q8); sts8(v, B0 + OFF_ADH, B0 + OFF_ADL, soff);
            uint4 v0 = make_uint4(0, 0, 0, 0), v1 = v0;
            if (hRow) {
                v0 = *(const uint4*)(hRow + (hq << 4));
                v1 = *(const uint4*)(hRow + (hq << 4) + 8);
            }
            *(uint4*)(B0 + offHL + hoff)      = v0;
            *(uint4*)(B0 + offHL + hoff + 16) = v1;
        }
        float acc[8];
#pragma unroll
        for (int i = 0; i < 8; i++) acc[i] = 0.f;

        for (int kt = 0; kt < 8; kt++) {
            __syncthreads();
            const uint32_t cb = smA + (uint32_t)((kt & 1) * BUF_B);
            char* NB = dsm + ((kt + 1) & 1) * BUF_B;
            const bool more = (kt < 7);
            const int k0n = (kt + 1) << 6;

            kstepB(cb, 0, a_off, b_off, acc);
            float4 v[2];
            if (more) ldg8(v, wdRow, k0n, q8);
            kstepB(cb, 1, a_off, b_off, acc);
            if (more) sts8(v, NB + OFF_ADH, NB + OFF_ADL, soff);
            kstepB(cb, 2, a_off, b_off, acc);
            uint4 v0 = make_uint4(0, 0, 0, 0), v1 = v0;
            if (more && hRow) {
                v0 = *(const uint4*)(hRow + k0n + (hq << 4));
                v1 = *(const uint4*)(hRow + k0n + (hq << 4) + 8);
            }
            kstepB(cb, 3, a_off, b_off, acc);
            if (more) {
                *(uint4*)(NB + offHL + hoff)      = v0;
                *(uint4*)(NB + offHL + hoff + 16) = v1;
            }
        }

        // epilogue: smem transpose -> coalesced f32 writeout
        __syncthreads();
        float* sm_y = (float*)dsm;            // [64 tok][68]
        {
            const int dr = (wm << 4) + (lane >> 2);
            const int tc = (wn << 4) + ((lane & 3) << 1);
#pragma unroll
            for (int nt = 0; nt < 2; nt++) {
#pragma unroll
                for (int q = 0; q < 4; q++) {
                    int d = dr + ((q >> 1) << 3);
                    int t = tc + (nt << 3) + (q & 1);
                    sm_y[t * 68 + d] = acc[nt * 4 + q];
                }
            }
        }
        __syncthreads();
        {
            const int ec = ent[r8];
            if (ec >= 0) {
                const float* src = sm_y + r8 * 68 + (q8 << 3);
                float* dst = g_Y + (size_t)ec * D_DIM + dc * 64 + (q8 << 3);
                *(float4*)(dst)     = *(const float4*)(src);
                *(float4*)(dst + 4) = *(const float4*)(src + 4);
            }
        }
    }
}

// ---------------- 5: weighted combine ----------------------------------------
__global__ void combine_kernel(float* __restrict__ out)
{
    const int t = blockIdx.x;
    const int d = threadIdx.x << 2;
    const float w0 = g_topk_w[t * 4 + 0];
    const float w1 = g_topk_w[t * 4 + 1];
    const float w2 = g_topk_w[t * 4 + 2];
    const float w3 = g_topk_w[t * 4 + 3];
    const float* yb = g_Y + (size_t)t * 4 * D_DIM;
    float4 y0 = *(const float4*)(yb + 0 * D_DIM + d);
    float4 y1 = *(const float4*)(yb + 1 * D_DIM + d);
    float4 y2 = *(const float4*)(yb + 2 * D_DIM + d);
    float4 y3 = *(const float4*)(yb + 3 * D_DIM + d);
    float4 o;
    o.x = w0 * y0.x + w1 * y1.x + w2 * y2.x + w3 * y3.x;
    o.y = w0 * y0.y + w1 * y1.y + w2 * y2.y + w3 * y3.y;
    o.z = w0 * y0.z + w1 * y1.z + w2 * y2.z + w3 * y3.z;
    o.w = w0 * y0.w + w1 * y1.w + w2 * y2.w + w3 * y3.w;
    *(float4*)(out + (size_t)t * D_DIM + d) = o;
}

// ---------------- launch ------------------------------------------------------
extern "C" void kernel_launch(void* const* d_in, const int* in_sizes, int n_in,
                              void* d_out, int out_size)
{
    (void)in_sizes; (void)n_in; (void)out_size;
    const float* x  = (const float*)d_in[0];
    const float* gw = (const float*)d_in[1];
    const float* wg = (const float*)d_in[2];
    const float* wu = (const float*)d_in[3];
    const float* wd = (const float*)d_in[4];
    float* out = (float*)d_out;

    const int smemA = 2 * BUF_A;   // 110592 -> 2 CTAs/SM (221 KB)
    const int smemB = 2 * BUF_B;   //  73728 -> 2 CTAs/SM (reg-limited)
    cudaFuncSetAttribute(stageA_mma, cudaFuncAttributeMaxDynamicSharedMemorySize, smemA);
    cudaFuncSetAttribute(stageB_mma, cudaFuncAttributeMaxDynamicSharedMemorySize, smemB);

    logits_kernel <<<32, 256>>>(x, gw);
    topk_kernel   <<<T_TOK, 32>>>();
    stageA_mma    <<<dim3(8, E_EXP), 512, smemA>>>(x, wg, wu);
    stageB_mma    <<<dim3(16, E_EXP), 512, smemB>>>(wd);
    combine_kernel<<<T_TOK, 256>>>(out);
}

// round 12
// speedup vs baseline: 1.6707x; 1.6707x over previous
#include <cuda_runtime.h>
#include <cuda_bf16.h>
#include <math.h>
#include <stdint.h>

#define T_TOK 512
#define D_DIM 1024
#define E_EXP 64
#define F_INT 512
#define TOPK  4

#define ROWB 144   // 64 bf16 = 128B data + 16B pad: conflict-free ldmatrix, swizzle-free
#define NTOK 64    // token tile; act-gating skips unused 16-token columns

// ---------------- persistent device scratch ----------------------------------
__device__ float g_logits[T_TOK * E_EXP];
__device__ float g_topk_w[T_TOK * TOPK];
__device__ int   g_exp_cnt[E_EXP];
__device__ int   g_exp_tok[E_EXP * T_TOK];                 // entry = token*4 + slot
__device__ __nv_bfloat16 g_Hhi[T_TOK * TOPK * F_INT];      // 2 MB
__device__ __nv_bfloat16 g_Hlo[T_TOK * TOPK * F_INT];      // 2 MB
__device__ float g_Y[T_TOK * TOPK * D_DIM];                // 8 MB

// ---------------- helpers -----------------------------------------------------
__device__ __forceinline__ uint32_t smem_u32(const void* p) {
    uint32_t a;
    asm("{ .reg .u64 t; cvta.to.shared.u64 t, %1; cvt.u32.u64 %0, t; }" : "=r"(a) : "l"(p));
    return a;
}
__device__ __forceinline__ void ldm4(uint32_t* r, uint32_t a) {
    asm volatile("ldmatrix.sync.aligned.m8n8.x4.shared.b16 {%0,%1,%2,%3}, [%4];"
        : "=r"(r[0]), "=r"(r[1]), "=r"(r[2]), "=r"(r[3]) : "r"(a));
}
__device__ __forceinline__ void mma16816(float* d, const uint32_t* a, const uint32_t* b) {
    asm volatile("mma.sync.aligned.m16n8k16.row.col.f32.bf16.bf16.f32 "
        "{%0,%1,%2,%3}, {%4,%5,%6,%7}, {%8,%9}, {%0,%1,%2,%3};"
        : "+f"(d[0]), "+f"(d[1]), "+f"(d[2]), "+f"(d[3])
        : "r"(a[0]), "r"(a[1]), "r"(a[2]), "r"(a[3]), "r"(b[0]), "r"(b[1]));
}
__device__ __forceinline__ uint32_t pack_bf2(__nv_bfloat16 a, __nv_bfloat16 b) {
    return (uint32_t)__bfloat16_as_ushort(a) | ((uint32_t)__bfloat16_as_ushort(b) << 16);
}
// split 8 contiguous fp32 into 16B bf16-hi + 16B bf16-lo
__device__ __forceinline__ void cvt_split8(const float4* v, uint4& h, uint4& l) {
    const float* f = (const float*)v;
    uint32_t hp[4], lp[4];
#pragma unroll
    for (int i = 0; i < 4; i++) {
        float a = f[2 * i], b = f[2 * i + 1];
        __nv_bfloat16 ha = __float2bfloat16(a), hb = __float2bfloat16(b);
        hp[i] = pack_bf2(ha, hb);
        lp[i] = pack_bf2(__float2bfloat16(a - __bfloat162float(ha)),
                         __float2bfloat16(b - __bfloat162float(hb)));
    }
    h = make_uint4(hp[0], hp[1], hp[2], hp[3]);
    l = make_uint4(lp[0], lp[1], lp[2], lp[3]);
}
__device__ __forceinline__ void sts8(const float4* v, char* hi, char* lo, int off) {
    uint4 h, l;
    cvt_split8(v, h, l);
    *(uint4*)(hi + off) = h;
    *(uint4*)(lo + off) = l;
}
// thread owns 8 contiguous floats of a [64 x 64] fp32 chunk: r = tid>>3, q = tid&7
__device__ __forceinline__ void ldg8(float4* v, const float* rowbase, int k0, int q) {
    v[0] = *(const float4*)(rowbase + k0 + (q << 3));
    v[1] = *(const float4*)(rowbase + k0 + (q << 3) + 4);
}

// ---------------- 1: router logits (block 0 also zeroes expert counts) --------
__global__ __launch_bounds__(256) void logits_kernel(
    const float* __restrict__ x, const float* __restrict__ gw)
{
    const int tblk = blockIdx.x * 16;
    const int tid  = threadIdx.x;
    if (blockIdx.x == 0 && tid < E_EXP) g_exp_cnt[tid] = 0;
    __shared__ __align__(16) float As[32][20];
    __shared__ __align__(16) float Bs[32][68];
    const int ttok = (tid >> 5) << 1;
    const int te   = (tid & 31) << 1;
    float acc00 = 0.f, acc01 = 0.f, acc10 = 0.f, acc11 = 0.f;

    for (int k0 = 0; k0 < D_DIM; k0 += 32) {
        if (tid < 128) {
            int tok = tid >> 3, kk4 = tid & 7;
            float4 v = *(const float4*)(x + (size_t)(tblk + tok) * D_DIM + k0 + (kk4 << 2));
            As[(kk4 << 2) + 0][tok] = v.x;
            As[(kk4 << 2) + 1][tok] = v.y;
            As[(kk4 << 2) + 2][tok] = v.z;
            As[(kk4 << 2) + 3][tok] = v.w;
        }
#pragma unroll
        for (int j = 0; j < 2; j++) {
            int idx = tid + (j << 8);
            int r = idx >> 3, kk4 = idx & 7;
            float4 v = *(const float4*)(gw + (size_t)r * D_DIM + k0 + (kk4 << 2));
            Bs[(kk4 << 2) + 0][r] = v.x;
            Bs[(kk4 << 2) + 1][r] = v.y;
            Bs[(kk4 << 2) + 2][r] = v.z;
            Bs[(kk4 << 2) + 3][r] = v.w;
        }
        __syncthreads();
#pragma unroll
        for (int kk = 0; kk < 32; kk++) {
            float a0 = As[kk][ttok], a1 = As[kk][ttok + 1];
            float b0 = Bs[kk][te],   b1 = Bs[kk][te + 1];
            acc00 += a0 * b0; acc01 += a0 * b1;
            acc10 += a1 * b0; acc11 += a1 * b1;
        }
        __syncthreads();
    }
    g_logits[(size_t)(tblk + ttok)     * E_EXP + te]     = acc00;
    g_logits[(size_t)(tblk + ttok)     * E_EXP + te + 1] = acc01;
    g_logits[(size_t)(tblk + ttok + 1) * E_EXP + te]     = acc10;
    g_logits[(size_t)(tblk + ttok + 1) * E_EXP + te + 1] = acc11;
}

// ---------------- 2: per-token top-4 + renorm + expert lists ------------------
__global__ void topk_kernel()
{
    const int t = blockIdx.x;
    const int lane = threadIdx.x;
    float c0 = g_logits[t * E_EXP + lane];
    float c1 = g_logits[t * E_EXP + lane + 32];
    float selv[4]; int seli[4];
#pragma unroll
    for (int s = 0; s < 4; s++) {
        float bv; int bi;
        if (c0 >= c1) { bv = c0; bi = lane; } else { bv = c1; bi = lane + 32; }
#pragma unroll
        for (int off = 16; off > 0; off >>= 1) {
            float ov = __shfl_xor_sync(0xffffffffu, bv, off);
            int   oi = __shfl_xor_sync(0xffffffffu, bi, off);
            if (ov > bv || (ov == bv && oi < bi)) { bv = ov; bi = oi; }
        }
        selv[s] = bv; seli[s] = bi;
        if (bi == lane)      c0 = -3.0e38f;
        if (bi == lane + 32) c1 = -3.0e38f;
    }
    if (lane == 0) {
        float m = selv[0];
        float ew[4]; float sum = 0.f;
#pragma unroll
        for (int s = 0; s < 4; s++) { ew[s] = expf(selv[s] - m); sum += ew[s]; }
        float inv = 1.f / sum;
#pragma unroll
        for (int s = 0; s < 4; s++) {
            g_topk_w[t * 4 + s] = ew[s] * inv;
            int ee = seli[s];
            int pos = atomicAdd(&g_exp_cnt[ee], 1);
            g_exp_tok[ee * T_TOK + pos] = t * 4 + s;
        }
    }
}

// ---------------- 3: Stage A — HMMA gate/up GEMM + in-register SiLU -----------
// CTA = (fchunk 0..7, expert), 512 threads, 2 CTAs/SM.
// Tile: 64 f x (act*16 <= 64) tok. Warp grid 4(M) x 4(N); warp tile [16 x 16].
// Warps with wn >= act skip all tensor work (cnt-adaptive N).
#define OFF_AGH 0
#define OFF_AGL 9216
#define OFF_AUH 18432
#define OFF_AUL 27648
#define OFF_BH  36864
#define OFF_BL  46080
#define BUF_A   55296

__device__ __forceinline__ void kstepA(uint32_t cb, int s, int a_off, int b_off,
                                       float* accg, float* accu)
{
    const int so = s << 5;
    uint32_t agh[4], agl[4], auh[4], aul[4], bh[4], bl[4];
    ldm4(agh, cb + OFF_AGH + a_off + so);
    ldm4(agl, cb + OFF_AGL + a_off + so);
    ldm4(auh, cb + OFF_AUH + a_off + so);
    ldm4(aul, cb + OFF_AUL + a_off + so);
    ldm4(bh,  cb + OFF_BH  + b_off + so);
    ldm4(bl,  cb + OFF_BL  + b_off + so);
#pragma unroll
    for (int nt = 0; nt < 2; nt++) {
        mma16816(accg + nt * 4, agh, bh + nt * 2);
        mma16816(accg + nt * 4, agl, bh + nt * 2);
        mma16816(accg + nt * 4, agh, bl + nt * 2);
        mma16816(accu + nt * 4, auh, bh + nt * 2);
        mma16816(accu + nt * 4, aul, bh + nt * 2);
        mma16816(accu + nt * 4, auh, bl + nt * 2);
    }
}

__global__ __launch_bounds__(512, 2) void stageA_mma(
    const float* __restrict__ x,
    const float* __restrict__ wg,
    const float* __restrict__ wu)
{
    const int e = blockIdx.y, fc = blockIdx.x;
    const int cnt = g_exp_cnt[e];
    if (cnt == 0) return;
    extern __shared__ __align__(16) char dsm[];
    __shared__ int ent[NTOK];
    const int tid = threadIdx.x, wid = tid >> 5, lane = tid & 31;
    const int wm = wid >> 2, wn = wid & 3;
    const uint32_t smA = smem_u32(dsm);

    const float* wgB = wg + ((size_t)e * F_INT + fc * 64) * D_DIM;
    const float* wuB = wu + ((size_t)e * F_INT + fc * 64) * D_DIM;

    const int a_off = ((wm << 4) + (lane & 15)) * ROWB + ((lane >> 4) << 4);
    const int b_off = ((wn << 4) + ((lane >> 4) << 3) + (lane & 7)) * ROWB
                    + (((lane >> 3) & 1) << 4);
    const int r8 = tid >> 3, q8 = tid & 7;          // loader: row, 8-float segment
    const int soff = r8 * ROWB + (q8 << 4);
    const float* wgRow = wgB + (size_t)r8 * D_DIM;
    const float* wuRow = wuB + (size_t)r8 * D_DIM;

    for (int base = 0; base < cnt; base += NTOK) {
        __syncthreads();
        if (tid < NTOK) ent[tid] = (base + tid < cnt) ? g_exp_tok[e * T_TOK + base + tid] : -1;
        __syncthreads();

        const int rem = cnt - base;
        const int act = min(4, ((rem < NTOK ? rem : NTOK) + 15) >> 4);  // active 16-tok cols
        const bool mmaOn   = (wn < act);
        const bool stageTok = (r8 < (act << 4));

        const int en0 = ent[r8];
        const float* xRow = (en0 >= 0) ? (x + (size_t)(en0 >> 2) * D_DIM) : 0;

        {   // prologue: chunk 0 -> buffer 0
            char* B0 = dsm;
            float4 v[2];
            ldg8(v, wgRow, 0, q8); sts8(v, B0 + OFF_AGH, B0 + OFF_AGL, soff);
            ldg8(v, wuRow, 0, q8); sts8(v, B0 + OFF_AUH, B0 + OFF_AUL, soff);
            if (stageTok) {
                if (xRow) ldg8(v, xRow, 0, q8);
                else { v[0] = make_float4(0.f, 0.f, 0.f, 0.f); v[1] = v[0]; }
                sts8(v, B0 + OFF_BH, B0 + OFF_BL, soff);
            }
        }
        float accg[8], accu[8];
#pragma unroll
        for (int i = 0; i < 8; i++) { accg[i] = 0.f; accu[i] = 0.f; }

        for (int kt = 0; kt < 16; kt++) {
            __syncthreads();
            const uint32_t cb = smA + (uint32_t)((kt & 1) * BUF_A);
            char* NB = dsm + ((kt + 1) & 1) * BUF_A;
            const bool more = (kt < 15);
            const int k0n = (kt + 1) << 6;

            if (mmaOn) kstepA(cb, 0, a_off, b_off, accg, accu);
            float4 vg[2], vu[2], vx[2];
            if (more) ldg8(vg, wgRow, k0n, q8);
            if (mmaOn) kstepA(cb, 1, a_off, b_off, accg, accu);
            if (more) {
                sts8(vg, NB + OFF_AGH, NB + OFF_AGL, soff);
                ldg8(vu, wuRow, k0n, q8);
            }
            if (mmaOn) kstepA(cb, 2, a_off, b_off, accg, accu);
            if (more) {
                sts8(vu, NB + OFF_AUH, NB + OFF_AUL, soff);
                if (stageTok) {
                    if (xRow) ldg8(vx, xRow, k0n, q8);
                    else { vx[0] = make_float4(0.f, 0.f, 0.f, 0.f); vx[1] = vx[0]; }
                }
            }
            if (mmaOn) kstepA(cb, 3, a_off, b_off, accg, accu);
            if (more && stageTok) sts8(vx, NB + OFF_BH, NB + OFF_BL, soff);
        }

        // epilogue: silu(g)*u in regs -> smem transpose -> coalesced bf16 hi/lo
        __syncthreads();
        float* sm_h = (float*)dsm;            // [64 tok][68]
        if (mmaOn) {
            const int fr = (wm << 4) + (lane >> 2);
            const int tc = (wn << 4) + ((lane & 3) << 1);
#pragma unroll
            for (int nt = 0; nt < 2; nt++) {
#pragma unroll
                for (int q = 0; q < 4; q++) {
                    int f = fr + ((q >> 1) << 3);
                    int t = tc + (nt << 3) + (q & 1);
                    float g = accg[nt * 4 + q], u = accu[nt * 4 + q];
                    float h = g / (1.f + __expf(-g)) * u;
                    sm_h[t * 68 + f] = h;
                }
            }
        }
        __syncthreads();
        {
            const int ec = ent[r8];
            if (ec >= 0) {
                const float4* src = (const float4*)(sm_h + r8 * 68 + (q8 << 3));
                uint4 h, l;
                float4 v[2] = { src[0], src[1] };
                cvt_split8(v, h, l);
                *(uint4*)(g_Hhi + (size_t)ec * F_INT + fc * 64 + (q8 << 3)) = h;
                *(uint4*)(g_Hlo + (size_t)ec * F_INT + fc * 64 + (q8 << 3)) = l;
            }
        }
    }
}

// ---------------- 4: Stage B — HMMA down GEMM --------------------------------
// CTA = (dchunk 0..15, expert), 512 threads, 2 CTAs/SM.
// Tile: 64 d x (act*16) tok. Warp tile [16 x 16], cnt-adaptive N.
#define OFF_ADH 0
#define OFF_ADL 9216
#define OFF_BBH 18432
#define OFF_BBL 27648
#define BUF_B   36864

__device__ __forceinline__ void kstepB(uint32_t cb, int s, int a_off, int b_off, float* acc)
{
    const int so = s << 5;
    uint32_t adh[4], adl[4], bh[4], bl[4];
    ldm4(adh, cb + OFF_ADH + a_off + so);
    ldm4(adl, cb + OFF_ADL + a_off + so);
    ldm4(bh,  cb + OFF_BBH + b_off + so);
    ldm4(bl,  cb + OFF_BBL + b_off + so);
#pragma unroll
    for (int nt = 0; nt < 2; nt++) {
        mma16816(acc + nt * 4, adh, bh + nt * 2);
        mma16816(acc + nt * 4, adl, bh + nt * 2);
        mma16816(acc + nt * 4, adh, bl + nt * 2);
    }
}

__global__ __launch_bounds__(512, 2) void stageB_mma(const float* __restrict__ wd)
{
    const int e = blockIdx.y, dc = blockIdx.x;
    const int cnt = g_exp_cnt[e];
    if (cnt == 0) return;
    extern __shared__ __align__(16) char dsm[];
    __shared__ int ent[NTOK];
    const int tid = threadIdx.x, wid = tid >> 5, lane = tid & 31;
    const int wm = wid >> 2, wn = wid & 3;
    const uint32_t smA = smem_u32(dsm);

    const float* wdB = wd + ((size_t)e * D_DIM + dc * 64) * F_INT;
    const int a_off = ((wm << 4) + (lane & 15)) * ROWB + ((lane >> 4) << 4);
    const int b_off = ((wn << 4) + ((lane >> 4) << 3) + (lane & 7)) * ROWB
                    + (((lane >> 3) & 1) << 4);
    const int r8 = tid >> 3, q8 = tid & 7;
    const int soff = r8 * ROWB + (q8 << 4);
    const float* wdRow = wdB + (size_t)r8 * F_INT;
    // H gather mapping: 256 threads per (hi|lo) plane, 32B per thread
    const int hidx = tid & 255, hr = hidx >> 2, hq = hidx & 3;
    const int hoff = hr * ROWB + (hq << 5);
    const int offHL = (tid < 256) ? OFF_BBH : OFF_BBL;

    for (int base = 0; base < cnt; base += NTOK) {
        __syncthreads();
        if (tid < NTOK) ent[tid] = (base + tid < cnt) ? g_exp_tok[e * T_TOK + base + tid] : -1;
        __syncthreads();

        const int rem = cnt - base;
        const int act = min(4, ((rem < NTOK ? rem : NTOK) + 15) >> 4);
        const bool mmaOn = (wn < act);
        const bool stageH = (hr < (act << 4));

        const int enH = ent[hr];
        const __nv_bfloat16* hRow = 0;
        if (enH >= 0) hRow = ((tid < 256) ? g_Hhi : g_Hlo) + (size_t)enH * F_INT;

        {   // prologue: chunk 0 -> buffer 0
            char* B0 = dsm;
            float4 v[2];
            ldg8(v, wdRow, 0, q8); sts8(v, B0 + OFF_ADH, B0 + OFF_ADL, soff);
            if (stageH) {
                uint4 v0 = make_uint4(0, 0, 0, 0), v1 = v0;
                if (hRow) {
                    v0 = *(const uint4*)(hRow + (hq << 4));
                    v1 = *(const uint4*)(hRow + (hq << 4) + 8);
                }
                *(uint4*)(B0 + offHL + hoff)      = v0;
                *(uint4*)(B0 + offHL + hoff + 16) = v1;
            }
        }
        float acc[8];
#pragma unroll
        for (int i = 0; i < 8; i++) acc[i] = 0.f;

        for (int kt = 0; kt < 8; kt++) {
            __syncthreads();
            const uint32_t cb = smA + (uint32_t)((kt & 1) * BUF_B);
            char* NB = dsm + ((kt + 1) & 1) * BUF_B;
            const bool more = (kt < 7);
            const int k0n = (kt + 1) << 6;

            if (mmaOn) kstepB(cb, 0, a_off, b_off, acc);
            float4 v[2];
            if (more) ldg8(v, wdRow, k0n, q8);
            if (mmaOn) kstepB(cb, 1, a_off, b_off, acc);
            if (more) sts8(v, NB + OFF_ADH, NB + OFF_ADL, soff);
            if (mmaOn) kstepB(cb, 2, a_off, b_off, acc);
            uint4 v0 = make_uint4(0, 0, 0, 0), v1 = v0;
            if (more && stageH && hRow) {
                v0 = *(const uint4*)(hRow + k0n + (hq << 4));
                v1 = *(const uint4*)(hRow + k0n + (hq << 4) + 8);
            }
            if (mmaOn) kstepB(cb, 3, a_off, b_off, acc);
            if (more && stageH) {
                *(uint4*)(NB + offHL + hoff)      = v0;
                *(uint4*)(NB + offHL + hoff + 16) = v1;
            }
        }

        // epilogue: smem transpose -> coalesced f32 writeout
        __syncthreads();
        float* sm_y = (float*)dsm;            // [64 tok][68]
        if (mmaOn) {
            const int dr = (wm << 4) + (lane >> 2);
            const int tc = (wn << 4) + ((lane & 3) << 1);
#pragma unroll
            for (int nt = 0; nt < 2; nt++) {
#pragma unroll
                for (int q = 0; q < 4; q++) {
                    int d = dr + ((q >> 1) << 3);
                    int t = tc + (nt << 3) + (q & 1);
                    sm_y[t * 68 + d] = acc[nt * 4 + q];
                }
            }
        }
        __syncthreads();
        {
            const int ec = ent[r8];
            if (ec >= 0) {
                const float* src = sm_y + r8 * 68 + (q8 << 3);
                float* dst = g_Y + (size_t)ec * D_DIM + dc * 64 + (q8 << 3);
                *(float4*)(dst)     = *(const float4*)(src);
                *(float4*)(dst + 4) = *(const float4*)(src + 4);
            }
        }
    }
}

// ---------------- 5: weighted combine ----------------------------------------
__global__ void combine_kernel(float* __restrict__ out)
{
    const int t = blockIdx.x;
    const int d = threadIdx.x << 2;
    const float w0 = g_topk_w[t * 4 + 0];
    const float w1 = g_topk_w[t * 4 + 1];
    const float w2 = g_topk_w[t * 4 + 2];
    const float w3 = g_topk_w[t * 4 + 3];
    const float* yb = g_Y + (size_t)t * 4 * D_DIM;
    float4 y0 = *(const float4*)(yb + 0 * D_DIM + d);
    float4 y1 = *(const float4*)(yb + 1 * D_DIM + d);
    float4 y2 = *(const float4*)(yb + 2 * D_DIM + d);
    float4 y3 = *(const float4*)(yb + 3 * D_DIM + d);
    float4 o;
    o.x = w0 * y0.x + w1 * y1.x + w2 * y2.x + w3 * y3.x;
    o.y = w0 * y0.y + w1 * y1.y + w2 * y2.y + w3 * y3.y;
    o.z = w0 * y0.z + w1 * y1.z + w2 * y2.z + w3 * y3.z;
    o.w = w0 * y0.w + w1 * y1.w + w2 * y2.w + w3 * y3.w;
    *(float4*)(out + (size_t)t * D_DIM + d) = o;
}

// ---------------- launch ------------------------------------------------------
extern "C" void kernel_launch(void* const* d_in, const int* in_sizes, int n_in,
                              void* d_out, int out_size)
{
    (void)in_sizes; (void)n_in; (void)out_size;
    const float* x  = (const float*)d_in[0];
    const float* gw = (const float*)d_in[1];
    const float* wg = (const float*)d_in[2];
    const float* wu = (const float*)d_in[3];
    const float* wd = (const float*)d_in[4];
    float* out = (float*)d_out;

    const int smemA = 2 * BUF_A;   // 110592 -> 2 CTAs/SM
    const int smemB = 2 * BUF_B;   //  73728 -> 2 CTAs/SM (reg-limited)
    cudaFuncSetAttribute(stageA_mma, cudaFuncAttributeMaxDynamicSharedMemorySize, smemA);
    cudaFuncSetAttribute(stageB_mma, cudaFuncAttributeMaxDynamicSharedMemorySize, smemB);

    logits_kernel <<<32, 256>>>(x, gw);
    topk_kernel   <<<T_TOK, 32>>>();
    stageA_mma    <<<dim3(8, E_EXP), 512, smemA>>>(x, wg, wu);
    stageB_mma    <<<dim3(16, E_EXP), 512, smemB>>>(wd);
    combine_kernel<<<T_TOK, 256>>>(out);
}

// round 13
// speedup vs baseline: 2.1548x; 1.2898x over previous
#include <cuda_runtime.h>
#include <cuda_fp16.h>
#include <math.h>
#include <stdint.h>

#define T_TOK 512
#define D_DIM 1024
#define E_EXP 64
#define F_INT 512
#define TOPK  4

#define ROWB 144   // 64 fp16 = 128B data + 16B pad: conflict-free ldmatrix, swizzle-free
#define NTOK 64    // token tile; act-gating skips unused 16-token columns

// ---------------- persistent device scratch ----------------------------------
__device__ float g_logits[T_TOK * E_EXP];
__device__ float g_topk_w[T_TOK * TOPK];
__device__ int   g_exp_cnt[E_EXP];
__device__ int   g_exp_tok[E_EXP * T_TOK];                 // entry = token*4 + slot
__device__ __half g_H[T_TOK * TOPK * F_INT];               // 2 MB (fp16, single plane)
__device__ float g_Y[T_TOK * TOPK * D_DIM];                // 8 MB

// ---------------- helpers -----------------------------------------------------
__device__ __forceinline__ uint32_t smem_u32(const void* p) {
    uint32_t a;
    asm("{ .reg .u64 t; cvta.to.shared.u64 t, %1; cvt.u32.u64 %0, t; }" : "=r"(a) : "l"(p));
    return a;
}
__device__ __forceinline__ void ldm4(uint32_t* r, uint32_t a) {
    asm volatile("ldmatrix.sync.aligned.m8n8.x4.shared.b16 {%0,%1,%2,%3}, [%4];"
        : "=r"(r[0]), "=r"(r[1]), "=r"(r[2]), "=r"(r[3]) : "r"(a));
}
__device__ __forceinline__ void mma16816(float* d, const uint32_t* a, const uint32_t* b) {
    asm volatile("mma.sync.aligned.m16n8k16.row.col.f32.f16.f16.f32 "
        "{%0,%1,%2,%3}, {%4,%5,%6,%7}, {%8,%9}, {%0,%1,%2,%3};"
        : "+f"(d[0]), "+f"(d[1]), "+f"(d[2]), "+f"(d[3])
        : "r"(a[0]), "r"(a[1]), "r"(a[2]), "r"(a[3]), "r"(b[0]), "r"(b[1]));
}
__device__ __forceinline__ uint32_t pack_h2(float a, float b) {
    __half2 h = __floats2half2_rn(a, b);
    return *reinterpret_cast<uint32_t*>(&h);
}
// split 8 contiguous fp32 into 16B fp16-hi + 16B fp16-lo
__device__ __forceinline__ void cvt_split8(const float4* v, uint4& h, uint4& l) {
    const float* f = (const float*)v;
    uint32_t hp[4], lp[4];
#pragma unroll
    for (int i = 0; i < 4; i++) {
        float a = f[2 * i], b = f[2 * i + 1];
        __half ha = __float2half_rn(a), hb = __float2half_rn(b);
        hp[i] = (uint32_t)__half_as_ushort(ha) | ((uint32_t)__half_as_ushort(hb) << 16);
        lp[i] = pack_h2(a - __half2float(ha), b - __half2float(hb));
    }
    h = make_uint4(hp[0], hp[1], hp[2], hp[3]);
    l = make_uint4(lp[0], lp[1], lp[2], lp[3]);
}
// 8 fp32 -> 8 fp16 (hi only)
__device__ __forceinline__ void cvt_h8(const float4* v, uint4& h) {
    const float* f = (const float*)v;
    h = make_uint4(pack_h2(f[0], f[1]), pack_h2(f[2], f[3]),
                   pack_h2(f[4], f[5]), pack_h2(f[6], f[7]));
}
__device__ __forceinline__ void sts8(const float4* v, char* hi, char* lo, int off) {
    uint4 h, l;
    cvt_split8(v, h, l);
    *(uint4*)(hi + off) = h;
    *(uint4*)(lo + off) = l;
}
// thread owns 8 contiguous floats: r = tid>>3, q = tid&7
__device__ __forceinline__ void ldg8(float4* v, const float* rowbase, int k0, int q) {
    v[0] = *(const float4*)(rowbase + k0 + (q << 3));
    v[1] = *(const float4*)(rowbase + k0 + (q << 3) + 4);
}

// ---------------- 1: router logits (block 0 also zeroes expert counts) --------
// 64 CTAs x 8 tokens: thread = (tok 0..7, 2 experts)
__global__ __launch_bounds__(256) void logits_kernel(
    const float* __restrict__ x, const float* __restrict__ gw)
{
    const int tblk = blockIdx.x * 8;
    const int tid  = threadIdx.x;
    if (blockIdx.x == 0 && tid < E_EXP) g_exp_cnt[tid] = 0;
    __shared__ __align__(16) float As[32][12];
    __shared__ __align__(16) float Bs[32][68];
    const int ttok = tid >> 5;          // 0..7
    const int te   = (tid & 31) << 1;   // 0..62
    float acc0 = 0.f, acc1 = 0.f;

    for (int k0 = 0; k0 < D_DIM; k0 += 32) {
        if (tid < 64) {
            int tok = tid >> 3, kk4 = tid & 7;
            float4 v = *(const float4*)(x + (size_t)(tblk + tok) * D_DIM + k0 + (kk4 << 2));
            As[(kk4 << 2) + 0][tok] = v.x;
            As[(kk4 << 2) + 1][tok] = v.y;
            As[(kk4 << 2) + 2][tok] = v.z;
            As[(kk4 << 2) + 3][tok] = v.w;
        }
#pragma unroll
        for (int j = 0; j < 2; j++) {
            int idx = tid + (j << 8);
            int r = idx >> 3, kk4 = idx & 7;
            float4 v = *(const float4*)(gw + (size_t)r * D_DIM + k0 + (kk4 << 2));
            Bs[(kk4 << 2) + 0][r] = v.x;
            Bs[(kk4 << 2) + 1][r] = v.y;
            Bs[(kk4 << 2) + 2][r] = v.z;
            Bs[(kk4 << 2) + 3][r] = v.w;
        }
        __syncthreads();
#pragma unroll
        for (int kk = 0; kk < 32; kk++) {
            float a = As[kk][ttok];
            acc0 += a * Bs[kk][te];
            acc1 += a * Bs[kk][te + 1];
        }
        __syncthreads();
    }
    g_logits[(size_t)(tblk + ttok) * E_EXP + te]     = acc0;
    g_logits[(size_t)(tblk + ttok) * E_EXP + te + 1] = acc1;
}

// ---------------- 2: per-token top-4 + renorm + expert lists ------------------
__global__ void topk_kernel()
{
    const int t = blockIdx.x;
    const int lane = threadIdx.x;
    float c0 = g_logits[t * E_EXP + lane];
    float c1 = g_logits[t * E_EXP + lane + 32];
    float selv[4]; int seli[4];
#pragma unroll
    for (int s = 0; s < 4; s++) {
        float bv; int bi;
        if (c0 >= c1) { bv = c0; bi = lane; } else { bv = c1; bi = lane + 32; }
#pragma unroll
        for (int off = 16; off > 0; off >>= 1) {
            float ov = __shfl_xor_sync(0xffffffffu, bv, off);
            int   oi = __shfl_xor_sync(0xffffffffu, bi, off);
            if (ov > bv || (ov == bv && oi < bi)) { bv = ov; bi = oi; }
        }
        selv[s] = bv; seli[s] = bi;
        if (bi == lane)      c0 = -3.0e38f;
        if (bi == lane + 32) c1 = -3.0e38f;
    }
    if (lane == 0) {
        float m = selv[0];
        float ew[4]; float sum = 0.f;
#pragma unroll
        for (int s = 0; s < 4; s++) { ew[s] = expf(selv[s] - m); sum += ew[s]; }
        float inv = 1.f / sum;
#pragma unroll
        for (int s = 0; s < 4; s++) {
            g_topk_w[t * 4 + s] = ew[s] * inv;
            int ee = seli[s];
            int pos = atomicAdd(&g_exp_cnt[ee], 1);
            g_exp_tok[ee * T_TOK + pos] = t * 4 + s;
        }
    }
}

// ---------------- 3: Stage A — HMMA gate/up GEMM + in-register SiLU -----------
// CTA = (fchunk 0..7, expert), 512 threads, 2 CTAs/SM.
// Weights fp16 hi+lo (2 planes each for gate/up); tokens fp16 hi only.
// Tile: 64 f x (act*16) tok. Warp grid 4(M) x 4(N); warp tile [16 x 16].
#define OFF_AGH 0
#define OFF_AGL 9216
#define OFF_AUH 18432
#define OFF_AUL 27648
#define OFF_BH  36864
#define BUF_A   46080

__device__ __forceinline__ void kstepA(uint32_t cb, int s, int a_off, int b_off,
                                       float* accg, float* accu)
{
    const int so = s << 5;
    uint32_t agh[4], agl[4], auh[4], aul[4], bh[4];
    ldm4(agh, cb + OFF_AGH + a_off + so);
    ldm4(agl, cb + OFF_AGL + a_off + so);
    ldm4(auh, cb + OFF_AUH + a_off + so);
    ldm4(aul, cb + OFF_AUL + a_off + so);
    ldm4(bh,  cb + OFF_BH  + b_off + so);
#pragma unroll
    for (int nt = 0; nt < 2; nt++) {
        mma16816(accg + nt * 4, agh, bh + nt * 2);
        mma16816(accg + nt * 4, agl, bh + nt * 2);
        mma16816(accu + nt * 4, auh, bh + nt * 2);
        mma16816(accu + nt * 4, aul, bh + nt * 2);
    }
}

__global__ __launch_bounds__(512, 2) void stageA_mma(
    const float* __restrict__ x,
    const float* __restrict__ wg,
    const float* __restrict__ wu)
{
    const int e = blockIdx.y, fc = blockIdx.x;
    const int cnt = g_exp_cnt[e];
    if (cnt == 0) return;
    extern __shared__ __align__(16) char dsm[];
    __shared__ int ent[NTOK];
    const int tid = threadIdx.x, wid = tid >> 5, lane = tid & 31;
    const int wm = wid >> 2, wn = wid & 3;
    const uint32_t smA = smem_u32(dsm);

    const float* wgB = wg + ((size_t)e * F_INT + fc * 64) * D_DIM;
    const float* wuB = wu + ((size_t)e * F_INT + fc * 64) * D_DIM;

    const int a_off = ((wm << 4) + (lane & 15)) * ROWB + ((lane >> 4) << 4);
    const int b_off = ((wn << 4) + ((lane >> 4) << 3) + (lane & 7)) * ROWB
                    + (((lane >> 3) & 1) << 4);
    const int r8 = tid >> 3, q8 = tid & 7;          // loader: row, 8-float segment
    const int soff = r8 * ROWB + (q8 << 4);
    const float* wgRow = wgB + (size_t)r8 * D_DIM;
    const float* wuRow = wuB + (size_t)r8 * D_DIM;

    for (int base = 0; base < cnt; base += NTOK) {
        __syncthreads();
        if (tid < NTOK) ent[tid] = (base + tid < cnt) ? g_exp_tok[e * T_TOK + base + tid] : -1;
        __syncthreads();

        const int rem = cnt - base;
        const int act = min(4, ((rem < NTOK ? rem : NTOK) + 15) >> 4);  // active 16-tok cols
        const bool mmaOn    = (wn < act);
        const bool stageTok = (r8 < (act << 4));

        const int en0 = ent[r8];
        const float* xRow = (en0 >= 0) ? (x + (size_t)(en0 >> 2) * D_DIM) : 0;

        {   // prologue: chunk 0 -> buffer 0
            char* B0 = dsm;
            float4 v[2];
            ldg8(v, wgRow, 0, q8); sts8(v, B0 + OFF_AGH, B0 + OFF_AGL, soff);
            ldg8(v, wuRow, 0, q8); sts8(v, B0 + OFF_AUH, B0 + OFF_AUL, soff);
            if (stageTok) {
                if (xRow) ldg8(v, xRow, 0, q8);
                else { v[0] = make_float4(0.f, 0.f, 0.f, 0.f); v[1] = v[0]; }
                uint4 h; cvt_h8(v, h);
                *(uint4*)(B0 + OFF_BH + soff) = h;
            }
        }
        float accg[8], accu[8];
#pragma unroll
        for (int i = 0; i < 8; i++) { accg[i] = 0.f; accu[i] = 0.f; }

        for (int kt = 0; kt < 16; kt++) {
            __syncthreads();
            const uint32_t cb = smA + (uint32_t)((kt & 1) * BUF_A);
            char* NB = dsm + ((kt + 1) & 1) * BUF_A;
            const bool more = (kt < 15);
            const int k0n = (kt + 1) << 6;

            if (mmaOn) kstepA(cb, 0, a_off, b_off, accg, accu);
            float4 vg[2], vu[2], vx[2];
            if (more) ldg8(vg, wgRow, k0n, q8);
            if (mmaOn) kstepA(cb, 1, a_off, b_off, accg, accu);
            if (more) {
                sts8(vg, NB + OFF_AGH, NB + OFF_AGL, soff);
                ldg8(vu, wuRow, k0n, q8);
            }
            if (mmaOn) kstepA(cb, 2, a_off, b_off, accg, accu);
            if (more) {
                sts8(vu, NB + OFF_AUH, NB + OFF_AUL, soff);
                if (stageTok) {
                    if (xRow) ldg8(vx, xRow, k0n, q8);
                    else { vx[0] = make_float4(0.f, 0.f, 0.f, 0.f); vx[1] = vx[0]; }
                }
            }
            if (mmaOn) kstepA(cb, 3, a_off, b_off, accg, accu);
            if (more && stageTok) {
                uint4 h; cvt_h8(vx, h);
                *(uint4*)(NB + OFF_BH + soff) = h;
            }
        }

        // epilogue: silu(g)*u in regs -> smem transpose -> coalesced fp16 writeout
        __syncthreads();
        float* sm_h = (float*)dsm;            // [64 tok][68]
        if (mmaOn) {
            const int fr = (wm << 4) + (lane >> 2);
            const int tc = (wn << 4) + ((lane & 3) << 1);
#pragma unroll
            for (int nt = 0; nt < 2; nt++) {
#pragma unroll
                for (int q = 0; q < 4; q++) {
                    int f = fr + ((q >> 1) << 3);
                    int t = tc + (nt << 3) + (q & 1);
                    float g = accg[nt * 4 + q], u = accu[nt * 4 + q];
                    float h = g / (1.f + __expf(-g)) * u;
                    sm_h[t * 68 + f] = h;
                }
            }
        }
        __syncthreads();
        {
            const int ec = ent[r8];
            if (ec >= 0) {
                const float4* src = (const float4*)(sm_h + r8 * 68 + (q8 << 3));
                float4 v[2] = { src[0], src[1] };
                uint4 h; cvt_h8(v, h);
                *(uint4*)(g_H + (size_t)ec * F_INT + fc * 64 + (q8 << 3)) = h;
            }
        }
    }
}

// ---------------- 4: Stage B — HMMA down GEMM --------------------------------
// CTA = (dchunk 0..15, expert), 512 threads, 2 CTAs/SM.
// wd fp16 hi+lo; H fp16 single plane. Tile: 64 d x (act*16) tok.
#define OFF_ADH 0
#define OFF_ADL 9216
#define OFF_BBH 18432
#define BUF_B   27648

__device__ __forceinline__ void kstepB(uint32_t cb, int s, int a_off, int b_off, float* acc)
{
    const int so = s << 5;
    uint32_t adh[4], adl[4], bh[4];
    ldm4(adh, cb + OFF_ADH + a_off + so);
    ldm4(adl, cb + OFF_ADL + a_off + so);
    ldm4(bh,  cb + OFF_BBH + b_off + so);
#pragma unroll
    for (int nt = 0; nt < 2; nt++) {
        mma16816(acc + nt * 4, adh, bh + nt * 2);
        mma16816(acc + nt * 4, adl, bh + nt * 2);
    }
}

__global__ __launch_bounds__(512, 2) void stageB_mma(const float* __restrict__ wd)
{
    const int e = blockIdx.y, dc = blockIdx.x;
    const int cnt = g_exp_cnt[e];
    if (cnt == 0) return;
    extern __shared__ __align__(16) char dsm[];
    __shared__ int ent[NTOK];
    const int tid = threadIdx.x, wid = tid >> 5, lane = tid & 31;
    const int wm = wid >> 2, wn = wid & 3;
    const uint32_t smA = smem_u32(dsm);

    const float* wdB = wd + ((size_t)e * D_DIM + dc * 64) * F_INT;
    const int a_off = ((wm << 4) + (lane & 15)) * ROWB + ((lane >> 4) << 4);
    const int b_off = ((wn << 4) + ((lane >> 4) << 3) + (lane & 7)) * ROWB
                    + (((lane >> 3) & 1) << 4);
    const int r8 = tid >> 3, q8 = tid & 7;
    const int soff = r8 * ROWB + (q8 << 4);
    const float* wdRow = wdB + (size_t)r8 * F_INT;

    for (int base = 0; base < cnt; base += NTOK) {
        __syncthreads();
        if (tid < NTOK) ent[tid] = (base + tid < cnt) ? g_exp_tok[e * T_TOK + base + tid] : -1;
        __syncthreads();

        const int rem = cnt - base;
        const int act = min(4, ((rem < NTOK ? rem : NTOK) + 15) >> 4);
        const bool mmaOn  = (wn < act);
        const bool stageH = (r8 < (act << 4));

        const int enH = ent[r8];
        const __half* hRow = (enH >= 0) ? (g_H + (size_t)enH * F_INT) : 0;

        {   // prologue: chunk 0 -> buffer 0
            char* B0 = dsm;
            float4 v[2];
            ldg8(v, wdRow, 0, q8); sts8(v, B0 + OFF_ADH, B0 + OFF_ADL, soff);
            if (stageH) {
                uint4 vv = make_uint4(0, 0, 0, 0);
                if (hRow) vv = *(const uint4*)(hRow + (q8 << 3));
                *(uint4*)(B0 + OFF_BBH + soff) = vv;
            }
        }
        float acc[8];
#pragma unroll
        for (int i = 0; i < 8; i++) acc[i] = 0.f;

        for (int kt = 0; kt < 8; kt++) {
            __syncthreads();
            const uint32_t cb = smA + (uint32_t)((kt & 1) * BUF_B);
            char* NB = dsm + ((kt + 1) & 1) * BUF_B;
            const bool more = (kt < 7);
            const int k0n = (kt + 1) << 6;

            if (mmaOn) kstepB(cb, 0, a_off, b_off, acc);
            float4 v[2];
            if (more) ldg8(v, wdRow, k0n, q8);
            if (mmaOn) kstepB(cb, 1, a_off, b_off, acc);
            if (more) sts8(v, NB + OFF_ADH, NB + OFF_ADL, soff);
            if (mmaOn) kstepB(cb, 2, a_off, b_off, acc);
            uint4 vv = make_uint4(0, 0, 0, 0);
            if (more && stageH && hRow) vv = *(const uint4*)(hRow + k0n + (q8 << 3));
            if (mmaOn) kstepB(cb, 3, a_off, b_off, acc);
            if (more && stageH) *(uint4*)(NB + OFF_BBH + soff) = vv;
        }

        // epilogue: smem transpose -> coalesced f32 writeout
        __syncthreads();
        float* sm_y = (float*)dsm;            // [64 tok][68]
        if (mmaOn) {
            const int dr = (wm << 4) + (lane >> 2);
            const int tc = (wn << 4) + ((lane & 3) << 1);
#pragma unroll
            for (int nt = 0; nt < 2; nt++) {
#pragma unroll
                for (int q = 0; q < 4; q++) {
                    int d = dr + ((q >> 1) << 3);
                    int t = tc + (nt << 3) + (q & 1);
                    sm_y[t * 68 + d] = acc[nt * 4 + q];
                }
            }
        }
        __syncthreads();
        {
            const int ec = ent[r8];
            if (ec >= 0) {
                const float* src = sm_y + r8 * 68 + (q8 << 3);
                float* dst = g_Y + (size_t)ec * D_DIM + dc * 64 + (q8 << 3);
                *(float4*)(dst)     = *(const float4*)(src);
                *(float4*)(dst + 4) = *(const float4*)(src + 4);
            }
        }
    }
}

// ---------------- 5: weighted combine ----------------------------------------
__global__ void combine_kernel(float* __restrict__ out)
{
    const int t = blockIdx.x;
    const int d = threadIdx.x << 2;
    const float w0 = g_topk_w[t * 4 + 0];
    const float w1 = g_topk_w[t * 4 + 1];
    const float w2 = g_topk_w[t * 4 + 2];
    const float w3 = g_topk_w[t * 4 + 3];
    const float* yb = g_Y + (size_t)t * 4 * D_DIM;
    float4 y0 = *(const float4*)(yb + 0 * D_DIM + d);
    float4 y1 = *(const float4*)(yb + 1 * D_DIM + d);
    float4 y2 = *(const float4*)(yb + 2 * D_DIM + d);
    float4 y3 = *(const float4*)(yb + 3 * D_DIM + d);
    float4 o;
    o.x = w0 * y0.x + w1 * y1.x + w2 * y2.x + w3 * y3.x;
    o.y = w0 * y0.y + w1 * y1.y + w2 * y2.y + w3 * y3.y;
    o.z = w0 * y0.z + w1 * y1.z + w2 * y2.z + w3 * y3.z;
    o.w = w0 * y0.w + w1 * y1.w + w2 * y2.w + w3 * y3.w;
    *(float4*)(out + (size_t)t * D_DIM + d) = o;
}

// ---------------- launch ------------------------------------------------------
extern "C" void kernel_launch(void* const* d_in, const int* in_sizes, int n_in,
                              void* d_out, int out_size)
{
    (void)in_sizes; (void)n_in; (void)out_size;
    const float* x  = (const float*)d_in[0];
    const float* gw = (const float*)d_in[1];
    const float* wg = (const float*)d_in[2];
    const float* wu = (const float*)d_in[3];
    const float* wd = (const float*)d_in[4];
    float* out = (float*)d_out;

    const int smemA = 2 * BUF_A;   // 92160 -> 2 CTAs/SM (184 KB)
    const int smemB = 2 * BUF_B;   // 55296 -> 2 CTAs/SM (reg-limited)
    cudaFuncSetAttribute(stageA_mma, cudaFuncAttributeMaxDynamicSharedMemorySize, smemA);
    cudaFuncSetAttribute(stageB_mma, cudaFuncAttributeMaxDynamicSharedMemorySize, smemB);

    logits_kernel <<<64, 256>>>(x, gw);
    topk_kernel   <<<T_TOK, 32>>>();
    stageA_mma    <<<dim3(8, E_EXP), 512, smemA>>>(x, wg, wu);
    stageB_mma    <<<dim3(16, E_EXP), 512, smemB>>>(wd);
    combine_kernel<<<T_TOK, 256>>>(out);
}

// round 14
// speedup vs baseline: 2.1950x; 1.0186x over previous
#include <cuda_runtime.h>
#include <cuda_fp16.h>
#include <math.h>
#include <stdint.h>

#define T_TOK 512
#define D_DIM 1024
#define E_EXP 64
#define F_INT 512
#define TOPK  4

#define ROWB 144   // 64 fp16 = 128B data + 16B pad: conflict-free ldmatrix, swizzle-free
#define NTOK 64    // token tile; act-gating skips unused 16-token columns

// ---------------- persistent device scratch ----------------------------------
__device__ float g_logits[T_TOK * E_EXP];
__device__ float g_topk_w[T_TOK * TOPK];
__device__ int   g_exp_cnt[E_EXP];
__device__ int   g_exp_tok[E_EXP * T_TOK];                 // entry = token*4 + slot
__device__ __half g_H[T_TOK * TOPK * F_INT];               // 2 MB (fp16, single plane)
__device__ float g_Y[T_TOK * TOPK * D_DIM];                // 8 MB

// ---------------- helpers -----------------------------------------------------
__device__ __forceinline__ uint32_t smem_u32(const void* p) {
    uint32_t a;
    asm("{ .reg .u64 t; cvta.to.shared.u64 t, %1; cvt.u32.u64 %0, t; }" : "=r"(a) : "l"(p));
    return a;
}
__device__ __forceinline__ void ldm4(uint32_t* r, uint32_t a) {
    asm volatile("ldmatrix.sync.aligned.m8n8.x4.shared.b16 {%0,%1,%2,%3}, [%4];"
        : "=r"(r[0]), "=r"(r[1]), "=r"(r[2]), "=r"(r[3]) : "r"(a));
}
__device__ __forceinline__ void mma16816(float* d, const uint32_t* a, const uint32_t* b) {
    asm volatile("mma.sync.aligned.m16n8k16.row.col.f32.f16.f16.f32 "
        "{%0,%1,%2,%3}, {%4,%5,%6,%7}, {%8,%9}, {%0,%1,%2,%3};"
        : "+f"(d[0]), "+f"(d[1]), "+f"(d[2]), "+f"(d[3])
        : "r"(a[0]), "r"(a[1]), "r"(a[2]), "r"(a[3]), "r"(b[0]), "r"(b[1]));
}
__device__ __forceinline__ uint32_t pack_h2(float a, float b) {
    __half2 h = __floats2half2_rn(a, b);
    return *reinterpret_cast<uint32_t*>(&h);
}
// split 8 contiguous fp32 into 16B fp16-hi + 16B fp16-lo
__device__ __forceinline__ void cvt_split8(const float4* v, uint4& h, uint4& l) {
    const float* f = (const float*)v;
    uint32_t hp[4], lp[4];
#pragma unroll
    for (int i = 0; i < 4; i++) {
        float a = f[2 * i], b = f[2 * i + 1];
        __half ha = __float2half_rn(a), hb = __float2half_rn(b);
        hp[i] = (uint32_t)__half_as_ushort(ha) | ((uint32_t)__half_as_ushort(hb) << 16);
        lp[i] = pack_h2(a - __half2float(ha), b - __half2float(hb));
    }
    h = make_uint4(hp[0], hp[1], hp[2], hp[3]);
    l = make_uint4(lp[0], lp[1], lp[2], lp[3]);
}
// 8 fp32 -> 8 fp16 (hi only)
__device__ __forceinline__ void cvt_h8(const float4* v, uint4& h) {
    const float* f = (const float*)v;
    h = make_uint4(pack_h2(f[0], f[1]), pack_h2(f[2], f[3]),
                   pack_h2(f[4], f[5]), pack_h2(f[6], f[7]));
}
__device__ __forceinline__ void sts8(const float4* v, char* hi, char* lo, int off) {
    uint4 h, l;
    cvt_split8(v, h, l);
    *(uint4*)(hi + off) = h;
    *(uint4*)(lo + off) = l;
}
// thread owns 8 contiguous floats: r = tid>>3, q = tid&7
__device__ __forceinline__ void ldg8(float4* v, const float* rowbase, int k0, int q) {
    v[0] = *(const float4*)(rowbase + k0 + (q << 3));
    v[1] = *(const float4*)(rowbase + k0 + (q << 3) + 4);
}

// ---------------- 1: router logits (block 0 also zeroes expert counts) --------
__global__ __launch_bounds__(256) void logits_kernel(
    const float* __restrict__ x, const float* __restrict__ gw)
{
    const int tblk = blockIdx.x * 8;
    const int tid  = threadIdx.x;
    if (blockIdx.x == 0 && tid < E_EXP) g_exp_cnt[tid] = 0;
    __shared__ __align__(16) float As[32][12];
    __shared__ __align__(16) float Bs[32][68];
    const int ttok = tid >> 5;          // 0..7
    const int te   = (tid & 31) << 1;   // 0..62
    float acc0 = 0.f, acc1 = 0.f;

    for (int k0 = 0; k0 < D_DIM; k0 += 32) {
        if (tid < 64) {
            int tok = tid >> 3, kk4 = tid & 7;
            float4 v = *(const float4*)(x + (size_t)(tblk + tok) * D_DIM + k0 + (kk4 << 2));
            As[(kk4 << 2) + 0][tok] = v.x;
            As[(kk4 << 2) + 1][tok] = v.y;
            As[(kk4 << 2) + 2][tok] = v.z;
            As[(kk4 << 2) + 3][tok] = v.w;
        }
#pragma unroll
        for (int j = 0; j < 2; j++) {
            int idx = tid + (j << 8);
            int r = idx >> 3, kk4 = idx & 7;
            float4 v = *(const float4*)(gw + (size_t)r * D_DIM + k0 + (kk4 << 2));
            Bs[(kk4 << 2) + 0][r] = v.x;
            Bs[(kk4 << 2) + 1][r] = v.y;
            Bs[(kk4 << 2) + 2][r] = v.z;
            Bs[(kk4 << 2) + 3][r] = v.w;
        }
        __syncthreads();
#pragma unroll
        for (int kk = 0; kk < 32; kk++) {
            float a = As[kk][ttok];
            acc0 += a * Bs[kk][te];
            acc1 += a * Bs[kk][te + 1];
        }
        __syncthreads();
    }
    g_logits[(size_t)(tblk + ttok) * E_EXP + te]     = acc0;
    g_logits[(size_t)(tblk + ttok) * E_EXP + te + 1] = acc1;
}

// ---------------- 2: per-token top-4 + renorm + expert lists ------------------
__global__ void topk_kernel()
{
    const int t = blockIdx.x;
    const int lane = threadIdx.x;
    float c0 = g_logits[t * E_EXP + lane];
    float c1 = g_logits[t * E_EXP + lane + 32];
    float selv[4]; int seli[4];
#pragma unroll
    for (int s = 0; s < 4; s++) {
        float bv; int bi;
        if (c0 >= c1) { bv = c0; bi = lane; } else { bv = c1; bi = lane + 32; }
#pragma unroll
        for (int off = 16; off > 0; off >>= 1) {
            float ov = __shfl_xor_sync(0xffffffffu, bv, off);
            int   oi = __shfl_xor_sync(0xffffffffu, bi, off);
            if (ov > bv || (ov == bv && oi < bi)) { bv = ov; bi = oi; }
        }
        selv[s] = bv; seli[s] = bi;
        if (bi == lane)      c0 = -3.0e38f;
        if (bi == lane + 32) c1 = -3.0e38f;
    }
    if (lane == 0) {
        float m = selv[0];
        float ew[4]; float sum = 0.f;
#pragma unroll
        for (int s = 0; s < 4; s++) { ew[s] = expf(selv[s] - m); sum += ew[s]; }
        float inv = 1.f / sum;
#pragma unroll
        for (int s = 0; s < 4; s++) {
            g_topk_w[t * 4 + s] = ew[s] * inv;
            int ee = seli[s];
            int pos = atomicAdd(&g_exp_cnt[ee], 1);
            g_exp_tok[ee * T_TOK + pos] = t * 4 + s;
        }
    }
}

// ---------------- 3: Stage A — HMMA gate/up GEMM + in-register SiLU -----------
// CTA = (fchunk 0..7, expert), 512 threads, 2 CTAs/SM.
// Weights fp16 hi+lo; tokens fp16 hi only. All next-chunk LDGs front-batched.
#define OFF_AGH 0
#define OFF_AGL 9216
#define OFF_AUH 18432
#define OFF_AUL 27648
#define OFF_BH  36864
#define BUF_A   46080

__device__ __forceinline__ void kstepA(uint32_t cb, int s, int a_off, int b_off,
                                       float* accg, float* accu)
{
    const int so = s << 5;
    uint32_t agh[4], agl[4], auh[4], aul[4], bh[4];
    ldm4(agh, cb + OFF_AGH + a_off + so);
    ldm4(agl, cb + OFF_AGL + a_off + so);
    ldm4(auh, cb + OFF_AUH + a_off + so);
    ldm4(aul, cb + OFF_AUL + a_off + so);
    ldm4(bh,  cb + OFF_BH  + b_off + so);
#pragma unroll
    for (int nt = 0; nt < 2; nt++) {
        mma16816(accg + nt * 4, agh, bh + nt * 2);
        mma16816(accg + nt * 4, agl, bh + nt * 2);
        mma16816(accu + nt * 4, auh, bh + nt * 2);
        mma16816(accu + nt * 4, aul, bh + nt * 2);
    }
}

__global__ __launch_bounds__(512, 2) void stageA_mma(
    const float* __restrict__ x,
    const float* __restrict__ wg,
    const float* __restrict__ wu)
{
    const int e = blockIdx.y, fc = blockIdx.x;
    const int cnt = g_exp_cnt[e];
    if (cnt == 0) return;
    extern __shared__ __align__(16) char dsm[];
    __shared__ int ent[NTOK];
    const int tid = threadIdx.x, wid = tid >> 5, lane = tid & 31;
    const int wm = wid >> 2, wn = wid & 3;
    const uint32_t smA = smem_u32(dsm);

    const float* wgB = wg + ((size_t)e * F_INT + fc * 64) * D_DIM;
    const float* wuB = wu + ((size_t)e * F_INT + fc * 64) * D_DIM;

    const int a_off = ((wm << 4) + (lane & 15)) * ROWB + ((lane >> 4) << 4);
    const int b_off = ((wn << 4) + ((lane >> 4) << 3) + (lane & 7)) * ROWB
                    + (((lane >> 3) & 1) << 4);
    const int r8 = tid >> 3, q8 = tid & 7;          // loader: row, 8-float segment
    const int soff = r8 * ROWB + (q8 << 4);
    const float* wgRow = wgB + (size_t)r8 * D_DIM;
    const float* wuRow = wuB + (size_t)r8 * D_DIM;

    for (int base = 0; base < cnt; base += NTOK) {
        __syncthreads();
        if (tid < NTOK) ent[tid] = (base + tid < cnt) ? g_exp_tok[e * T_TOK + base + tid] : -1;
        __syncthreads();

        const int rem = cnt - base;
        const int act = min(4, ((rem < NTOK ? rem : NTOK) + 15) >> 4);  // active 16-tok cols
        const bool mmaOn    = (wn < act);
        const bool stageTok = (r8 < (act << 4));

        const int en0 = ent[r8];
        const float* xRow = (en0 >= 0) ? (x + (size_t)(en0 >> 2) * D_DIM) : 0;

        {   // prologue: chunk 0 -> buffer 0 (front-batched loads)
            char* B0 = dsm;
            float4 vg[2], vu[2], vx[2];
            ldg8(vg, wgRow, 0, q8);
            ldg8(vu, wuRow, 0, q8);
            if (stageTok) {
                if (xRow) ldg8(vx, xRow, 0, q8);
                else { vx[0] = make_float4(0.f, 0.f, 0.f, 0.f); vx[1] = vx[0]; }
            }
            sts8(vg, B0 + OFF_AGH, B0 + OFF_AGL, soff);
            sts8(vu, B0 + OFF_AUH, B0 + OFF_AUL, soff);
            if (stageTok) {
                uint4 h; cvt_h8(vx, h);
                *(uint4*)(B0 + OFF_BH + soff) = h;
            }
        }
        float accg[8], accu[8];
#pragma unroll
        for (int i = 0; i < 8; i++) { accg[i] = 0.f; accu[i] = 0.f; }

        for (int kt = 0; kt < 16; kt++) {
            __syncthreads();
            const uint32_t cb = smA + (uint32_t)((kt & 1) * BUF_A);
            char* NB = dsm + ((kt + 1) & 1) * BUF_A;
            const bool more = (kt < 15);
            const int k0n = (kt + 1) << 6;

            // front-batch ALL next-chunk loads: 6 LDG.128 in flight per thread
            float4 vg[2], vu[2], vx[2];
            if (more) {
                ldg8(vg, wgRow, k0n, q8);
                ldg8(vu, wuRow, k0n, q8);
                if (stageTok) {
                    if (xRow) ldg8(vx, xRow, k0n, q8);
                    else { vx[0] = make_float4(0.f, 0.f, 0.f, 0.f); vx[1] = vx[0]; }
                }
            }
            if (mmaOn) { kstepA(cb, 0, a_off, b_off, accg, accu);
                         kstepA(cb, 1, a_off, b_off, accg, accu); }
            if (more) sts8(vg, NB + OFF_AGH, NB + OFF_AGL, soff);
            if (mmaOn) kstepA(cb, 2, a_off, b_off, accg, accu);
            if (more) sts8(vu, NB + OFF_AUH, NB + OFF_AUL, soff);
            if (mmaOn) kstepA(cb, 3, a_off, b_off, accg, accu);
            if (more && stageTok) {
                uint4 h; cvt_h8(vx, h);
                *(uint4*)(NB + OFF_BH + soff) = h;
            }
        }

        // epilogue: silu(g)*u in regs -> smem transpose -> coalesced fp16 writeout
        __syncthreads();
        float* sm_h = (float*)dsm;            // [64 tok][68]
        if (mmaOn) {
            const int fr = (wm << 4) + (lane >> 2);
            const int tc = (wn << 4) + ((lane & 3) << 1);
#pragma unroll
            for (int nt = 0; nt < 2; nt++) {
#pragma unroll
                for (int q = 0; q < 4; q++) {
                    int f = fr + ((q >> 1) << 3);
                    int t = tc + (nt << 3) + (q & 1);
                    float g = accg[nt * 4 + q], u = accu[nt * 4 + q];
                    float h = g / (1.f + __expf(-g)) * u;
                    sm_h[t * 68 + f] = h;
                }
            }
        }
        __syncthreads();
        {
            const int ec = ent[r8];
            if (ec >= 0) {
                const float4* src = (const float4*)(sm_h + r8 * 68 + (q8 << 3));
                float4 v[2] = { src[0], src[1] };
                uint4 h; cvt_h8(v, h);
                *(uint4*)(g_H + (size_t)ec * F_INT + fc * 64 + (q8 << 3)) = h;
            }
        }
    }
}

// ---------------- 4: Stage B — HMMA down GEMM --------------------------------
// CTA = (dchunk 0..15, expert), 512 threads, 2 CTAs/SM. Front-batched loads.
#define OFF_ADH 0
#define OFF_ADL 9216
#define OFF_BBH 18432
#define BUF_B   27648

__device__ __forceinline__ void kstepB(uint32_t cb, int s, int a_off, int b_off, float* acc)
{
    const int so = s << 5;
    uint32_t adh[4], adl[4], bh[4];
    ldm4(adh, cb + OFF_ADH + a_off + so);
    ldm4(adl, cb + OFF_ADL + a_off + so);
    ldm4(bh,  cb + OFF_BBH + b_off + so);
#pragma unroll
    for (int nt = 0; nt < 2; nt++) {
        mma16816(acc + nt * 4, adh, bh + nt * 2);
        mma16816(acc + nt * 4, adl, bh + nt * 2);
    }
}

__global__ __launch_bounds__(512, 2) void stageB_mma(const float* __restrict__ wd)
{
    const int e = blockIdx.y, dc = blockIdx.x;
    const int cnt = g_exp_cnt[e];
    if (cnt == 0) return;
    extern __shared__ __align__(16) char dsm[];
    __shared__ int ent[NTOK];
    const int tid = threadIdx.x, wid = tid >> 5, lane = tid & 31;
    const int wm = wid >> 2, wn = wid & 3;
    const uint32_t smA = smem_u32(dsm);

    const float* wdB = wd + ((size_t)e * D_DIM + dc * 64) * F_INT;
    const int a_off = ((wm << 4) + (lane & 15)) * ROWB + ((lane >> 4) << 4);
    const int b_off = ((wn << 4) + ((lane >> 4) << 3) + (lane & 7)) * ROWB
                    + (((lane >> 3) & 1) << 4);
    const int r8 = tid >> 3, q8 = tid & 7;
    const int soff = r8 * ROWB + (q8 << 4);
    const float* wdRow = wdB + (size_t)r8 * F_INT;

    for (int base = 0; base < cnt; base += NTOK) {
        __syncthreads();
        if (tid < NTOK) ent[tid] = (base + tid < cnt) ? g_exp_tok[e * T_TOK + base + tid] : -1;
        __syncthreads();

        const int rem = cnt - base;
        const int act = min(4, ((rem < NTOK ? rem : NTOK) + 15) >> 4);
        const bool mmaOn  = (wn < act);
        const bool stageH = (r8 < (act << 4));

        const int enH = ent[r8];
        const __half* hRow = (enH >= 0) ? (g_H + (size_t)enH * F_INT) : 0;

        {   // prologue: chunk 0 -> buffer 0 (front-batched)
            char* B0 = dsm;
            float4 v[2];
            uint4 vv = make_uint4(0, 0, 0, 0);
            ldg8(v, wdRow, 0, q8);
            if (stageH && hRow) vv = *(const uint4*)(hRow + (q8 << 3));
            sts8(v, B0 + OFF_ADH, B0 + OFF_ADL, soff);
            if (stageH) *(uint4*)(B0 + OFF_BBH + soff) = vv;
        }
        float acc[8];
#pragma unroll
        for (int i = 0; i < 8; i++) acc[i] = 0.f;

        for (int kt = 0; kt < 8; kt++) {
            __syncthreads();
            const uint32_t cb = smA + (uint32_t)((kt & 1) * BUF_B);
            char* NB = dsm + ((kt + 1) & 1) * BUF_B;
            const bool more = (kt < 7);
            const int k0n = (kt + 1) << 6;

            // front-batch next-chunk loads: 3 LDG.128 in flight per thread
            float4 v[2];
            uint4 vv = make_uint4(0, 0, 0, 0);
            if (more) {
                ldg8(v, wdRow, k0n, q8);
                if (stageH && hRow) vv = *(const uint4*)(hRow + k0n + (q8 << 3));
            }
            if (mmaOn) { kstepB(cb, 0, a_off, b_off, acc);
                         kstepB(cb, 1, a_off, b_off, acc); }
            if (more) sts8(v, NB + OFF_ADH, NB + OFF_ADL, soff);
            if (mmaOn) { kstepB(cb, 2, a_off, b_off, acc);
                         kstepB(cb, 3, a_off, b_off, acc); }
            if (more && stageH) *(uint4*)(NB + OFF_BBH + soff) = vv;
        }

        // epilogue: smem transpose -> coalesced f32 writeout
        __syncthreads();
        float* sm_y = (float*)dsm;            // [64 tok][68]
        if (mmaOn) {
            const int dr = (wm << 4) + (lane >> 2);
            const int tc = (wn << 4) + ((lane & 3) << 1);
#pragma unroll
            for (int nt = 0; nt < 2; nt++) {
#pragma unroll
                for (int q = 0; q < 4; q++) {
                    int d = dr + ((q >> 1) << 3);
                    int t = tc + (nt << 3) + (q & 1);
                    sm_y[t * 68 + d] = acc[nt * 4 + q];
                }
            }
        }
        __syncthreads();
        {
            const int ec = ent[r8];
            if (ec >= 0) {
                const float* src = sm_y + r8 * 68 + (q8 << 3);
                float* dst = g_Y + (size_t)ec * D_DIM + dc * 64 + (q8 << 3);
                *(float4*)(dst)     = *(const float4*)(src);
                *(float4*)(dst + 4) = *(const float4*)(src + 4);
            }
        }
    }
}

// ---------------- 5: weighted combine ----------------------------------------
__global__ void combine_kernel(float* __restrict__ out)
{
    const int t = blockIdx.x;
    const int d = threadIdx.x << 2;
    const float w0 = g_topk_w[t * 4 + 0];
    const float w1 = g_topk_w[t * 4 + 1];
    const float w2 = g_topk_w[t * 4 + 2];
    const float w3 = g_topk_w[t * 4 + 3];
    const float* yb = g_Y + (size_t)t * 4 * D_DIM;
    float4 y0 = *(const float4*)(yb + 0 * D_DIM + d);
    float4 y1 = *(const float4*)(yb + 1 * D_DIM + d);
    float4 y2 = *(const float4*)(yb + 2 * D_DIM + d);
    float4 y3 = *(const float4*)(yb + 3 * D_DIM + d);
    float4 o;
    o.x = w0 * y0.x + w1 * y1.x + w2 * y2.x + w3 * y3.x;
    o.y = w0 * y0.y + w1 * y1.y + w2 * y2.y + w3 * y3.y;
    o.z = w0 * y0.z + w1 * y1.z + w2 * y2.z + w3 * y3.z;
    o.w = w0 * y0.w + w1 * y1.w + w2 * y2.w + w3 * y3.w;
    *(float4*)(out + (size_t)t * D_DIM + d) = o;
}

// ---------------- launch ------------------------------------------------------
extern "C" void kernel_launch(void* const* d_in, const int* in_sizes, int n_in,
                              void* d_out, int out_size)
{
    (void)in_sizes; (void)n_in; (void)out_size;
    const float* x  = (const float*)d_in[0];
    const float* gw = (const float*)d_in[1];
    const float* wg = (const float*)d_in[2];
    const float* wu = (const float*)d_in[3];
    const float* wd = (const float*)d_in[4];
    float* out = (float*)d_out;

    const int smemA = 2 * BUF_A;   // 92160 -> 2 CTAs/SM (184 KB)
    const int smemB = 2 * BUF_B;   // 55296 -> 2 CTAs/SM (reg-limited)
    cudaFuncSetAttribute(stageA_mma, cudaFuncAttributeMaxDynamicSharedMemorySize, smemA);
    cudaFuncSetAttribute(stageB_mma, cudaFuncAttributeMaxDynamicSharedMemorySize, smemB);

    logits_kernel <<<64, 256>>>(x, gw);
    topk_kernel   <<<T_TOK, 32>>>();
    stageA_mma    <<<dim3(8, E_EXP), 512, smemA>>>(x, wg, wu);
    stageB_mma    <<<dim3(16, E_EXP), 512, smemB>>>(wd);
    combine_kernel<<<T_TOK, 256>>>(out);
}